// round 13
// baseline (speedup 1.0000x reference)
#include <cuda_runtime.h>
#include <cuda_fp16.h>

// Guided filter, RADIUS=8, EPS=0.01, (8,3,1024,1024) fp32 — FULLY FUSED,
// single-sync software pipeline.
// Per iteration (production cursor q, output cursor o = q-9):
//   publish VX..VXY edges (for produce) AND Va/Vb edges (for out) -> ONE sync
//   -> out(o) from Va state [o-8, o+8] -> Va trail-subtract (ring row o-8)
//   -> produce(q): 4-series h-box -> (a,b) -> Va add + ring write
//   -> advance VX window.
// Ring is thread-private by construction (each thread reads only its own cols).

#define W     1024
#define Hh    1024
#define IMGS  24
#define HW    (Hh * W)
#define RAD   8
#define EPSF  0.01f
#define SEGR  64
#define SEGS  (Hh / SEGR)
#define TPB   128
#define NW    4
#define FULLM 0xffffffffu

#define RING_U (17 * 1024)
#define EDGE_F (2 * NW * 96)                     // parity, warp, 6 series x (pre8,suf8)
#define SMEM_BYTES (RING_U * 4 + EDGE_F * 4)     // 72704

__device__ __forceinline__ unsigned int pack_h2(float a, float b) {
    __half2 h = __floats2half2_rn(a, b);
    return *reinterpret_cast<unsigned int*>(&h);
}
__device__ __forceinline__ void dec_h2(unsigned int u, float& a, float& b) {
    __half2 h = *reinterpret_cast<__half2*>(&u);
    float2 f = __half22float2(h);
    a = f.x; b = f.y;
}

__device__ __forceinline__ void boxV(const float V[8], const float hsuf[8],
                                     const float hpre[8], int lane, float bx[8]) {
    float p[9]; p[0] = 0.f;
    #pragma unroll
    for (int j = 0; j < 8; j++) p[j + 1] = p[j] + V[j];
    float U = p[8];
    float sufL[8], preR[8];
    #pragma unroll
    for (int j = 0; j < 8; j++) {
        float t = __shfl_up_sync(FULLM, U - p[j], 1);
        sufL[j] = (lane == 0) ? hsuf[j] : t;
    }
    #pragma unroll
    for (int j = 0; j < 8; j++) {
        float t = __shfl_down_sync(FULLM, p[j + 1], 1);
        preR[j] = (lane == 31) ? hpre[j] : t;
    }
    #pragma unroll
    for (int j = 0; j < 8; j++) bx[j] = (sufL[j] + U) + preR[j];
}

__device__ __forceinline__ void write_edges(const float V[8], float* pre_dst,
                                            float* suf_dst, int lane) {
    if (lane == 0) {
        float t[8]; float acc = 0.f;
        #pragma unroll
        for (int j = 0; j < 8; j++) { acc += V[j]; t[j] = acc; }
        *(float4*)(pre_dst)     = make_float4(t[0], t[1], t[2], t[3]);
        *(float4*)(pre_dst + 4) = make_float4(t[4], t[5], t[6], t[7]);
    } else if (lane == 31) {
        float t[8]; float acc = 0.f;
        #pragma unroll
        for (int j = 7; j >= 0; j--) { acc += V[j]; t[j] = acc; }
        *(float4*)(suf_dst)     = make_float4(t[0], t[1], t[2], t[3]);
        *(float4*)(suf_dst + 4) = make_float4(t[4], t[5], t[6], t[7]);
    }
}

__device__ __forceinline__ void get_halo(const float* sufsrc, const float* presrc,
                                         int warp, int lane,
                                         float hsuf[8], float hpre[8]) {
    #pragma unroll
    for (int j = 0; j < 8; j++) { hsuf[j] = 0.f; hpre[j] = 0.f; }
    if (lane == 0) {
        if (warp > 0) {
            float4 a = *(const float4*)sufsrc, b = *(const float4*)(sufsrc + 4);
            hsuf[0]=a.x; hsuf[1]=a.y; hsuf[2]=a.z; hsuf[3]=a.w;
            hsuf[4]=b.x; hsuf[5]=b.y; hsuf[6]=b.z; hsuf[7]=b.w;
        }
    } else if (lane == 31) {
        if (warp < NW - 1) {
            float4 a = *(const float4*)presrc, b = *(const float4*)(presrc + 4);
            hpre[0]=a.x; hpre[1]=a.y; hpre[2]=a.z; hpre[3]=a.w;
            hpre[4]=b.x; hpre[5]=b.y; hpre[6]=b.z; hpre[7]=b.w;
        }
    }
}

template<int SGN>
__device__ __forceinline__ void addXY(const float* __restrict__ xr,
                                      const float* __restrict__ yr, int col0,
                                      float VX[8], float VY[8],
                                      float VXX[8], float VXY[8]) {
    float4 a0 = *(const float4*)(xr + col0), a1 = *(const float4*)(xr + col0 + 4);
    float4 b0 = *(const float4*)(yr + col0), b1 = *(const float4*)(yr + col0 + 4);
    float xv[8] = {a0.x,a0.y,a0.z,a0.w,a1.x,a1.y,a1.z,a1.w};
    float yv[8] = {b0.x,b0.y,b0.z,b0.w,b1.x,b1.y,b1.z,b1.w};
    #pragma unroll
    for (int j = 0; j < 8; j++) {
        if (SGN > 0) {
            VX[j] += xv[j]; VY[j] += yv[j];
            VXX[j] = fmaf(xv[j], xv[j], VXX[j]);
            VXY[j] = fmaf(xv[j], yv[j], VXY[j]);
        } else {
            VX[j] -= xv[j]; VY[j] -= yv[j];
            VXX[j] = fmaf(-xv[j], xv[j], VXX[j]);
            VXY[j] = fmaf(-xv[j], yv[j], VXY[j]);
        }
    }
}

__global__ void __launch_bounds__(TPB) kF(const float* __restrict__ x,
                                          const float* __restrict__ y,
                                          float* __restrict__ out) {
    extern __shared__ __align__(16) char smraw[];
    unsigned int* ring = (unsigned int*)smraw;           // [17][1024]
    float* edges = (float*)(smraw + RING_U * 4);         // [2][NW][96]

    int img  = blockIdx.y;
    int s    = blockIdx.x * SEGR;
    int warp = threadIdx.x >> 5;
    int lane = threadIdx.x & 31;
    int col0 = (warp << 8) + lane * 8;
    const float* xb = x + img * HW;
    const float* yb = y + img * HW;
    float* ob = out + img * HW;
    int wl = (warp > 0) ? warp - 1 : 0;
    int wr = (warp < NW - 1) ? warp + 1 : NW - 1;

    float VX[8], VY[8], VXX[8], VXY[8], Va[8], Vb[8];
    #pragma unroll
    for (int j = 0; j < 8; j++) {
        VX[j]=0.f; VY[j]=0.f; VXX[j]=0.f; VXY[j]=0.f; Va[j]=0.f; Vb[j]=0.f;
    }

    // init VX window for q0 = s-8: rows [max(0, s-16), s]
    for (int r = max(0, s - 16); r <= s; r++)
        addXY<+1>(xb + r * W, yb + r * W, col0, VX, VY, VXX, VXY);

    float inv_nx[8];
    #pragma unroll
    for (int j = 0; j < 8; j++) {
        int c = col0 + j;
        inv_nx[j] = __frcp_rn((float)(min(W - 1, c + RAD) - max(0, c - RAD) + 1));
    }

    // publish VX..VXY edges into parity buffer
    auto pubVX = [&](int par) {
        float* b = edges + par * (NW * 96) + warp * 96;
        write_edges(VX,  b +  0, b +  8, lane);
        write_edges(VY,  b + 16, b + 24, lane);
        write_edges(VXX, b + 32, b + 40, lane);
        write_edges(VXY, b + 48, b + 56, lane);
    };
    auto pubAB = [&](int par) {
        float* b = edges + par * (NW * 96) + warp * 96;
        write_edges(Va, b + 64, b + 72, lane);
        write_edges(Vb, b + 80, b + 88, lane);
    };

    // consume published VX edges -> a,b row q -> Va add + ring write
    auto produce = [&](int q, int par) {
        float* bl = edges + par * (NW * 96) + wl * 96;
        float* br = edges + par * (NW * 96) + wr * 96;
        float bx0[8], bx1[8], bx2[8], bx3[8], hsuf[8], hpre[8];
        get_halo(bl +  8, br +  0, warp, lane, hsuf, hpre);
        boxV(VX,  hsuf, hpre, lane, bx0);
        get_halo(bl + 24, br + 16, warp, lane, hsuf, hpre);
        boxV(VY,  hsuf, hpre, lane, bx1);
        get_halo(bl + 40, br + 32, warp, lane, hsuf, hpre);
        boxV(VXX, hsuf, hpre, lane, bx2);
        get_halo(bl + 56, br + 48, warp, lane, hsuf, hpre);
        boxV(VXY, hsuf, hpre, lane, bx3);

        float inv_ny = __frcp_rn((float)(min(Hh - 1, q + RAD) - max(0, q - RAD) + 1));
        unsigned int pk[8];
        #pragma unroll
        for (int j = 0; j < 8; j++) {
            float invN = inv_nx[j] * inv_ny;
            float mx = bx0[j] * invN, my = bx1[j] * invN;
            float varx = fmaf(-mx, mx, bx2[j] * invN);
            float cov  = fmaf(-mx, my, bx3[j] * invN);
            float a = __fdividef(cov, varx + EPSF);
            float b = fmaf(-a, mx, my);
            unsigned int u = pack_h2(a, b);
            pk[j] = u;
            float ad, bd; dec_h2(u, ad, bd);
            Va[j] += ad; Vb[j] += bd;
        }
        unsigned int* rp = ring + (q % 17) * 1024 + col0;
        *(uint4*)rp       = make_uint4(pk[0], pk[1], pk[2], pk[3]);
        *(uint4*)(rp + 4) = make_uint4(pk[4], pk[5], pk[6], pk[7]);
    };

    auto advVX = [&](int q) {            // after producing q, shift window to q+1
        int lead = q + 9;
        if (lead <= Hh - 1)
            addXY<+1>(xb + lead * W, yb + lead * W, col0, VX, VY, VXX, VXY);
        int tr = q - 8;
        if (tr >= 0)
            addXY<-1>(xb + tr * W, yb + tr * W, col0, VX, VY, VXX, VXY);
    };

    // ---- warm-up: produce a-rows q = s-8 .. s+8 (clipped at 0) ----
    for (int q = s - 8; q <= s + 8; q++) {
        if (q >= 0) {
            int par = q & 1;
            pubVX(par);
            __syncthreads();
            produce(q, par);
        }
        advVX(q);
    }

    // ---- main loop: ONE sync per output row ----
    for (int o = s; o < s + SEGR; o++) {
        int q = o + 9;
        int par = q & 1;
        bool prodq = (q <= Hh - 1);

        if (prodq) pubVX(par);
        pubAB(par);
        __syncthreads();

        // out(o) from Va = rows [max(0,o-8), o+8 (clipped)]
        {
            float* bl = edges + par * (NW * 96) + wl * 96;
            float* br = edges + par * (NW * 96) + wr * 96;
            float bxa[8], bxb[8], hsuf[8], hpre[8];
            get_halo(bl + 72, br + 64, warp, lane, hsuf, hpre);
            boxV(Va, hsuf, hpre, lane, bxa);
            get_halo(bl + 88, br + 80, warp, lane, hsuf, hpre);
            boxV(Vb, hsuf, hpre, lane, bxb);

            float inv_ny = __frcp_rn((float)(min(Hh - 1, o + RAD) - max(0, o - RAD) + 1));
            float4 x0 = *(const float4*)(xb + o * W + col0);
            float4 x1 = *(const float4*)(xb + o * W + col0 + 4);
            float xs[8] = {x0.x,x0.y,x0.z,x0.w,x1.x,x1.y,x1.z,x1.w};
            float os[8];
            #pragma unroll
            for (int j = 0; j < 8; j++) {
                float invN = inv_nx[j] * inv_ny;
                os[j] = fmaf(bxa[j] * invN, xs[j], bxb[j] * invN);
            }
            *(float4*)(ob + o * W + col0)     = make_float4(os[0], os[1], os[2], os[3]);
            *(float4*)(ob + o * W + col0 + 4) = make_float4(os[4], os[5], os[6], os[7]);
        }

        // Va trail-subtract: a-row t = o-8 (read ring BEFORE produce overwrites slot)
        int t = o - 8;
        if (t >= 0) {
            const unsigned int* rp = ring + (t % 17) * 1024 + col0;
            uint4 u0 = *(const uint4*)rp, u1 = *(const uint4*)(rp + 4);
            unsigned int uu[8] = {u0.x,u0.y,u0.z,u0.w,u1.x,u1.y,u1.z,u1.w};
            #pragma unroll
            for (int j = 0; j < 8; j++) {
                float ad, bd; dec_h2(uu[j], ad, bd);
                Va[j] -= ad; Vb[j] -= bd;
            }
        }

        if (prodq) {
            produce(q, par);
            advVX(q);
        }
    }
}

extern "C" void kernel_launch(void* const* d_in, const int* in_sizes, int n_in,
                              void* d_out, int out_size) {
    const float* x = (const float*)d_in[0];
    const float* y = (const float*)d_in[1];
    float* out = (float*)d_out;

    cudaFuncSetAttribute(kF, cudaFuncAttributeMaxDynamicSharedMemorySize,
                         SMEM_BYTES);
    dim3 grid(SEGS, IMGS);
    kF<<<grid, TPB, SMEM_BYTES>>>(x, y, out);
}

// round 14
// speedup vs baseline: 1.0480x; 1.0480x over previous
#include <cuda_runtime.h>
#include <cuda_fp16.h>

// Guided filter, RADIUS=8, EPS=0.01, (8,3,1024,1024) fp32.
// Two kernels, both VERTICAL-FIRST and fully WARP-AUTONOMOUS:
// each lane keeps vertical running sums V[ser][8] of its 8 columns; the warp's
// edge lanes (0 and 31) additionally maintain vertical sums of the 8 halo
// columns adjacent to the warp strip (loaded straight from global, predicated).
// One chain-free 17-wide horizontal box per output row; no smem, no syncs.
// kA: x,y -> (a,b) packed half2.  kB: (a,b),x -> out.

#define W     1024
#define Hh    1024
#define IMGS  24
#define HW    (Hh * W)
#define TOTAL (IMGS * HW)
#define RAD   8
#define EPSF  0.01f
#define SEGR  32
#define SEGS  (Hh / SEGR)
#define TPB   128
#define NW    4
#define FULLM 0xffffffffu

__device__ __align__(16) __half2 g_ab[TOTAL];

__device__ __forceinline__ unsigned int pack_h2(float a, float b) {
    __half2 h = __floats2half2_rn(a, b);
    return *reinterpret_cast<unsigned int*>(&h);
}
__device__ __forceinline__ void dec_h2(unsigned int u, float& a, float& b) {
    __half2 h = *reinterpret_cast<__half2*>(&u);
    float2 f = __half22float2(h);
    a = f.x; b = f.y;
}

// 17-wide horizontal box of per-lane vertical sums V[8]; halo vertical sums
// HALO[8] are meaningful on lanes 0 (left halo) and 31 (right halo).
__device__ __forceinline__ void boxV(const float V[8], const float HALO[8],
                                     int lane, float bx[8]) {
    float p[9]; p[0] = 0.f;
    #pragma unroll
    for (int j = 0; j < 8; j++) p[j + 1] = p[j] + V[j];
    float U = p[8];

    float hs[8], hp[8];
    hs[7] = HALO[7];
    #pragma unroll
    for (int j = 6; j >= 0; j--) hs[j] = hs[j + 1] + HALO[j];
    hp[0] = HALO[0];
    #pragma unroll
    for (int j = 1; j < 8; j++) hp[j] = hp[j - 1] + HALO[j];

    float sufL[8], preR[8];
    #pragma unroll
    for (int j = 0; j < 8; j++) {
        float t = __shfl_up_sync(FULLM, U - p[j], 1);
        sufL[j] = (lane == 0) ? hs[j] : t;
    }
    #pragma unroll
    for (int j = 0; j < 8; j++) {
        float t = __shfl_down_sync(FULLM, p[j + 1], 1);
        preR[j] = (lane == 31) ? hp[j] : t;
    }
    #pragma unroll
    for (int j = 0; j < 8; j++) bx[j] = (sufL[j] + U) + preR[j];
}

// ------------------------- kA --------------------------------------------
template<int SGN>
__device__ __forceinline__ void addXY(const float* __restrict__ xr,
                                      const float* __restrict__ yr,
                                      int col0, int hcol, bool hvalid,
                                      float VX[8], float VY[8],
                                      float VXX[8], float VXY[8],
                                      float HX[8], float HY[8],
                                      float HXX[8], float HXY[8]) {
    float4 a0 = *(const float4*)(xr + col0), a1 = *(const float4*)(xr + col0 + 4);
    float4 b0 = *(const float4*)(yr + col0), b1 = *(const float4*)(yr + col0 + 4);
    float xv[8] = {a0.x,a0.y,a0.z,a0.w,a1.x,a1.y,a1.z,a1.w};
    float yv[8] = {b0.x,b0.y,b0.z,b0.w,b1.x,b1.y,b1.z,b1.w};
    #pragma unroll
    for (int j = 0; j < 8; j++) {
        if (SGN > 0) {
            VX[j] += xv[j]; VY[j] += yv[j];
            VXX[j] = fmaf(xv[j], xv[j], VXX[j]);
            VXY[j] = fmaf(xv[j], yv[j], VXY[j]);
        } else {
            VX[j] -= xv[j]; VY[j] -= yv[j];
            VXX[j] = fmaf(-xv[j], xv[j], VXX[j]);
            VXY[j] = fmaf(-xv[j], yv[j], VXY[j]);
        }
    }
    if (hvalid) {
        float4 h0 = *(const float4*)(xr + hcol), h1 = *(const float4*)(xr + hcol + 4);
        float4 g0 = *(const float4*)(yr + hcol), g1 = *(const float4*)(yr + hcol + 4);
        float hx[8] = {h0.x,h0.y,h0.z,h0.w,h1.x,h1.y,h1.z,h1.w};
        float hy[8] = {g0.x,g0.y,g0.z,g0.w,g1.x,g1.y,g1.z,g1.w};
        #pragma unroll
        for (int j = 0; j < 8; j++) {
            if (SGN > 0) {
                HX[j] += hx[j]; HY[j] += hy[j];
                HXX[j] = fmaf(hx[j], hx[j], HXX[j]);
                HXY[j] = fmaf(hx[j], hy[j], HXY[j]);
            } else {
                HX[j] -= hx[j]; HY[j] -= hy[j];
                HXX[j] = fmaf(-hx[j], hx[j], HXX[j]);
                HXY[j] = fmaf(-hx[j], hy[j], HXY[j]);
            }
        }
    }
}

__global__ void __launch_bounds__(TPB) kA(const float* __restrict__ x,
                                          const float* __restrict__ y) {
    int img  = blockIdx.y;
    int s    = blockIdx.x * SEGR;
    int warp = threadIdx.x >> 5;
    int lane = threadIdx.x & 31;
    int C    = warp << 8;
    int col0 = C + lane * 8;
    const float* xb = x + img * HW;
    const float* yb = y + img * HW;

    int hcol = (lane == 0) ? (C - 8) : (C + 256);
    bool hvalid = ((lane == 0) || (lane == 31)) && hcol >= 0 && hcol + 7 < W;

    float VX[8], VY[8], VXX[8], VXY[8];
    float HX[8], HY[8], HXX[8], HXY[8];
    #pragma unroll
    for (int j = 0; j < 8; j++) {
        VX[j]=0.f; VY[j]=0.f; VXX[j]=0.f; VXY[j]=0.f;
        HX[j]=0.f; HY[j]=0.f; HXX[j]=0.f; HXY[j]=0.f;
    }

    for (int r = max(0, s - RAD); r <= s + RAD; r++)
        addXY<+1>(xb + r * W, yb + r * W, col0, hcol, hvalid,
                  VX, VY, VXX, VXY, HX, HY, HXX, HXY);

    float inv_nx[8];
    #pragma unroll
    for (int j = 0; j < 8; j++) {
        int c = col0 + j;
        inv_nx[j] = __frcp_rn((float)(min(W - 1, c + RAD) - max(0, c - RAD) + 1));
    }

    __half2* gab = g_ab + img * HW;

    for (int o = s; o < s + SEGR; o++) {
        float bx0[8], bx1[8], bx2[8], bx3[8];
        boxV(VX,  HX,  lane, bx0);
        boxV(VY,  HY,  lane, bx1);
        boxV(VXX, HXX, lane, bx2);
        boxV(VXY, HXY, lane, bx3);

        float inv_ny = __frcp_rn((float)(min(Hh - 1, o + RAD) - max(0, o - RAD) + 1));
        unsigned int pk[8];
        #pragma unroll
        for (int j = 0; j < 8; j++) {
            float invN = inv_nx[j] * inv_ny;
            float mx = bx0[j] * invN, my = bx1[j] * invN;
            float varx = fmaf(-mx, mx, bx2[j] * invN);
            float cov  = fmaf(-mx, my, bx3[j] * invN);
            float a = __fdividef(cov, varx + EPSF);
            float b = fmaf(-a, mx, my);
            pk[j] = pack_h2(a, b);
        }
        uint4 u0 = make_uint4(pk[0], pk[1], pk[2], pk[3]);
        uint4 u1 = make_uint4(pk[4], pk[5], pk[6], pk[7]);
        *(uint4*)(gab + o * W + col0)     = u0;
        *(uint4*)(gab + o * W + col0 + 4) = u1;

        int lead = o + RAD + 1, trail = o - RAD;
        if (lead < Hh)
            addXY<+1>(xb + lead * W, yb + lead * W, col0, hcol, hvalid,
                      VX, VY, VXX, VXY, HX, HY, HXX, HXY);
        if (trail >= 0)
            addXY<-1>(xb + trail * W, yb + trail * W, col0, hcol, hvalid,
                      VX, VY, VXX, VXY, HX, HY, HXX, HXY);
    }
}

// ------------------------- kB --------------------------------------------
template<int SGN>
__device__ __forceinline__ void addAB(const __half2* __restrict__ abr,
                                      int col0, int hcol, bool hvalid,
                                      float Va[8], float Vb[8],
                                      float Ha[8], float Hb[8]) {
    uint4 p0 = *(const uint4*)(abr + col0);
    uint4 p1 = *(const uint4*)(abr + col0 + 4);
    unsigned int u[8] = {p0.x,p0.y,p0.z,p0.w,p1.x,p1.y,p1.z,p1.w};
    #pragma unroll
    for (int j = 0; j < 8; j++) {
        float a, b; dec_h2(u[j], a, b);
        if (SGN > 0) { Va[j] += a; Vb[j] += b; }
        else         { Va[j] -= a; Vb[j] -= b; }
    }
    if (hvalid) {
        uint4 q0 = *(const uint4*)(abr + hcol);
        uint4 q1 = *(const uint4*)(abr + hcol + 4);
        unsigned int v[8] = {q0.x,q0.y,q0.z,q0.w,q1.x,q1.y,q1.z,q1.w};
        #pragma unroll
        for (int j = 0; j < 8; j++) {
            float a, b; dec_h2(v[j], a, b);
            if (SGN > 0) { Ha[j] += a; Hb[j] += b; }
            else         { Ha[j] -= a; Hb[j] -= b; }
        }
    }
}

__global__ void __launch_bounds__(TPB) kB(const float* __restrict__ x,
                                          float* __restrict__ out) {
    int img  = blockIdx.y;
    int s    = blockIdx.x * SEGR;
    int warp = threadIdx.x >> 5;
    int lane = threadIdx.x & 31;
    int C    = warp << 8;
    int col0 = C + lane * 8;
    const __half2* abr = g_ab + img * HW;
    const float* xb = x + img * HW;
    float* ob = out + img * HW;

    int hcol = (lane == 0) ? (C - 8) : (C + 256);
    bool hvalid = ((lane == 0) || (lane == 31)) && hcol >= 0 && hcol + 7 < W;

    float Va[8], Vb[8], Ha[8], Hb[8];
    #pragma unroll
    for (int j = 0; j < 8; j++) { Va[j]=0.f; Vb[j]=0.f; Ha[j]=0.f; Hb[j]=0.f; }

    for (int r = max(0, s - RAD); r <= s + RAD; r++)
        addAB<+1>(abr + r * W, col0, hcol, hvalid, Va, Vb, Ha, Hb);

    float inv_nx[8];
    #pragma unroll
    for (int j = 0; j < 8; j++) {
        int c = col0 + j;
        inv_nx[j] = __frcp_rn((float)(min(W - 1, c + RAD) - max(0, c - RAD) + 1));
    }

    for (int o = s; o < s + SEGR; o++) {
        float bxa[8], bxb[8];
        boxV(Va, Ha, lane, bxa);
        boxV(Vb, Hb, lane, bxb);

        float inv_ny = __frcp_rn((float)(min(Hh - 1, o + RAD) - max(0, o - RAD) + 1));
        float4 x0 = *(const float4*)(xb + o * W + col0);
        float4 x1 = *(const float4*)(xb + o * W + col0 + 4);
        float xs[8] = {x0.x,x0.y,x0.z,x0.w,x1.x,x1.y,x1.z,x1.w};
        float os[8];
        #pragma unroll
        for (int j = 0; j < 8; j++) {
            float invN = inv_nx[j] * inv_ny;
            os[j] = fmaf(bxa[j] * invN, xs[j], bxb[j] * invN);
        }
        *(float4*)(ob + o * W + col0)     = make_float4(os[0], os[1], os[2], os[3]);
        *(float4*)(ob + o * W + col0 + 4) = make_float4(os[4], os[5], os[6], os[7]);

        int lead = o + RAD + 1, trail = o - RAD;
        if (lead < Hh)
            addAB<+1>(abr + lead * W, col0, hcol, hvalid, Va, Vb, Ha, Hb);
        if (trail >= 0)
            addAB<-1>(abr + trail * W, col0, hcol, hvalid, Va, Vb, Ha, Hb);
    }
}

extern "C" void kernel_launch(void* const* d_in, const int* in_sizes, int n_in,
                              void* d_out, int out_size) {
    const float* x = (const float*)d_in[0];
    const float* y = (const float*)d_in[1];
    float* out = (float*)d_out;

    dim3 grid(SEGS, IMGS);
    kA<<<grid, TPB>>>(x, y);
    kB<<<grid, TPB>>>(x, out);
}